// round 1
// baseline (speedup 1.0000x reference)
#include <cuda_runtime.h>

#define BATCH 2
#define SEQ   2048
#define CH    768
#define HEADS 12
#define HDIM  64
#define ATT_SCALE 0.125f   // HDIM^-0.5

// ---------------- scratch (static device allocations; no cudaMalloc) -------
__device__ float g_xpart[BATCH * 16 * CH];
__device__ float g_xmean[BATCH * CH];
__device__ float g_u[BATCH * HEADS * CH];
__device__ float g_z[BATCH * HEADS * SEQ];
__device__ float g_attn[BATCH * HEADS * SEQ];   // softmax / SEQ
__device__ float g_V[BATCH * SEQ * CH];
__device__ float g_oa[BATCH * SEQ * CH];

// ---------------- 1a: partial sums of x over n ------------------------------
__global__ void xpart_kernel(const float* __restrict__ x) {
    int b = blockIdx.y;
    int chunk = blockIdx.x;           // 16 chunks of 128 rows
    const float* xb = x + ((size_t)b * SEQ + (size_t)chunk * 128) * CH;
    for (int c = threadIdx.x; c < CH; c += 256) {
        float s = 0.f;
        #pragma unroll 8
        for (int n = 0; n < 128; n++) s += xb[(size_t)n * CH + c];
        g_xpart[(b * 16 + chunk) * CH + c] = s;
    }
}

// ---------------- 1b: reduce partials -> mean -------------------------------
__global__ void xmean_kernel() {
    int b = blockIdx.x;
    int c = threadIdx.x;              // 768 threads
    float s = 0.f;
    #pragma unroll
    for (int k = 0; k < 16; k++) s += g_xpart[(b * 16 + k) * CH + c];
    g_xmean[b * CH + c] = s * (1.0f / SEQ);
}

// ---------------- 2: u[b,h,c] = SCALE * sum_d Wq[h*64+d,c] * K_avg[b,h,d] ---
__global__ void u_kernel(const float* __restrict__ Wq, const float* __restrict__ Wk) {
    int b = blockIdx.x / HEADS;
    int h = blockIdx.x % HEADS;
    __shared__ float xm[CH];
    __shared__ float kavg[HDIM];
    for (int c = threadIdx.x; c < CH; c += 256) xm[c] = g_xmean[b * CH + c];
    __syncthreads();
    if (threadIdx.x < HDIM) {
        const float* wk = Wk + (size_t)(h * HDIM + threadIdx.x) * CH;
        float s = 0.f;
        #pragma unroll 8
        for (int c = 0; c < CH; c++) s += xm[c] * wk[c];
        kavg[threadIdx.x] = s;
    }
    __syncthreads();
    for (int c = threadIdx.x; c < CH; c += 256) {
        float s = 0.f;
        #pragma unroll 8
        for (int d = 0; d < HDIM; d++)
            s += Wq[(size_t)(h * HDIM + d) * CH + c] * kavg[d];
        g_u[(b * HEADS + h) * CH + c] = s * ATT_SCALE;
    }
}

// ---------------- 3: z[b,h,n] = x[b,n,:] . u[b,h,:] --------------------------
__global__ void z_kernel(const float* __restrict__ x) {
    int bn = blockIdx.x;                       // b*SEQ + n
    int b = bn / SEQ;
    int n = bn % SEQ;
    __shared__ float xs[CH];
    const float* xr = x + (size_t)bn * CH;
    for (int c = threadIdx.x; c < CH; c += 384) xs[c] = xr[c];
    __syncthreads();
    int w = threadIdx.x >> 5;                  // 12 warps = 12 heads
    int lane = threadIdx.x & 31;
    const float* u = g_u + (size_t)(b * HEADS + w) * CH;
    float s = 0.f;
    #pragma unroll
    for (int c = lane; c < CH; c += 32) s += xs[c] * u[c];
    #pragma unroll
    for (int off = 16; off > 0; off >>= 1)
        s += __shfl_down_sync(0xffffffffu, s, off);
    if (lane == 0) g_z[(b * HEADS + w) * SEQ + n] = s;
}

// ---------------- 4: softmax over n per (b,h), fold 1/SEQ --------------------
__global__ void softmax_kernel() {
    __shared__ float red[256];
    int base = blockIdx.x * SEQ;
    int tid = threadIdx.x;
    float v[8];
    float m = -1e30f;
    #pragma unroll
    for (int k = 0; k < 8; k++) {
        v[k] = g_z[base + tid + k * 256];
        m = fmaxf(m, v[k]);
    }
    red[tid] = m; __syncthreads();
    for (int s = 128; s > 0; s >>= 1) {
        if (tid < s) red[tid] = fmaxf(red[tid], red[tid + s]);
        __syncthreads();
    }
    m = red[0]; __syncthreads();
    float sum = 0.f;
    #pragma unroll
    for (int k = 0; k < 8; k++) { v[k] = __expf(v[k] - m); sum += v[k]; }
    red[tid] = sum; __syncthreads();
    for (int s = 128; s > 0; s >>= 1) {
        if (tid < s) red[tid] += red[tid + s];
        __syncthreads();
    }
    float inv = 1.0f / (red[0] * (float)SEQ);
    #pragma unroll
    for (int k = 0; k < 8; k++) g_attn[base + tid + k * 256] = v[k] * inv;
}

// ---------------- GEMM: out[M,Nc] = A[M,K] @ W[Nc,K]^T (+bias) ---------------
// 128x128 tile, BK=16, 256 threads, 8x8 per thread.
template <bool BIAS>
__global__ void __launch_bounds__(256) gemm_abt_kernel(
    const float* __restrict__ A, const float* __restrict__ W,
    const float* __restrict__ bias, float* __restrict__ out,
    int M, int Nc, int K)
{
    __shared__ float As[16][132];
    __shared__ float Bs[16][132];
    int tid = threadIdx.x;
    int tx = tid & 15;           // 16 -> 8 cols each
    int ty = tid >> 4;           // 16 -> 8 rows each
    int m0 = blockIdx.y * 128;
    int n0 = blockIdx.x * 128;

    float acc[8][8];
    #pragma unroll
    for (int r = 0; r < 8; r++)
        #pragma unroll
        for (int s = 0; s < 8; s++) acc[r][s] = 0.f;

    for (int kt = 0; kt < K; kt += 16) {
        #pragma unroll
        for (int q = 0; q < 2; q++) {
            int f = tid + q * 256;
            int row = f >> 2;            // 0..127
            int kq = f & 3;              // 0..3
            float4 va = *(const float4*)(A + (size_t)(m0 + row) * K + kt + kq * 4);
            As[kq * 4 + 0][row] = va.x;
            As[kq * 4 + 1][row] = va.y;
            As[kq * 4 + 2][row] = va.z;
            As[kq * 4 + 3][row] = va.w;
            float4 vb = *(const float4*)(W + (size_t)(n0 + row) * K + kt + kq * 4);
            Bs[kq * 4 + 0][row] = vb.x;
            Bs[kq * 4 + 1][row] = vb.y;
            Bs[kq * 4 + 2][row] = vb.z;
            Bs[kq * 4 + 3][row] = vb.w;
        }
        __syncthreads();
        #pragma unroll
        for (int kk = 0; kk < 16; kk++) {
            float4 a0 = *(const float4*)&As[kk][ty * 8];
            float4 a1 = *(const float4*)&As[kk][ty * 8 + 4];
            float4 b0 = *(const float4*)&Bs[kk][tx * 8];
            float4 b1 = *(const float4*)&Bs[kk][tx * 8 + 4];
            float av[8] = {a0.x, a0.y, a0.z, a0.w, a1.x, a1.y, a1.z, a1.w};
            float bv[8] = {b0.x, b0.y, b0.z, b0.w, b1.x, b1.y, b1.z, b1.w};
            #pragma unroll
            for (int r = 0; r < 8; r++)
                #pragma unroll
                for (int s = 0; s < 8; s++)
                    acc[r][s] += av[r] * bv[s];
        }
        __syncthreads();
    }

    #pragma unroll
    for (int r = 0; r < 8; r++) {
        int row = m0 + ty * 8 + r;
        float* op = out + (size_t)row * Nc + n0 + tx * 8;
        float4 o0, o1;
        if (BIAS) {
            const float* bp = bias + n0 + tx * 8;
            o0 = make_float4(acc[r][0] + bp[0], acc[r][1] + bp[1],
                             acc[r][2] + bp[2], acc[r][3] + bp[3]);
            o1 = make_float4(acc[r][4] + bp[4], acc[r][5] + bp[5],
                             acc[r][6] + bp[6], acc[r][7] + bp[7]);
        } else {
            o0 = make_float4(acc[r][0], acc[r][1], acc[r][2], acc[r][3]);
            o1 = make_float4(acc[r][4], acc[r][5], acc[r][6], acc[r][7]);
        }
        *(float4*)op = o0;
        *(float4*)(op + 4) = o1;
    }
}

// ---------------- circulant: oa[b,i,c] = sum_j attn[b,h(c),(j-i)%N] * V[b,j,c]
// tile: 128 (i) x 64 (c == one head), BK(j)=16, 128 threads, 8x8 per thread.
__global__ void __launch_bounds__(128) circ_kernel() {
    __shared__ float A2[2 * SEQ];    // doubled attn row: A2[x] = attn[x & 2047]
    __shared__ float Vs[16][68];
    int b = blockIdx.z;
    int i0 = blockIdx.x * 128;
    int c0 = blockIdx.y * 64;
    int h = c0 / HDIM;
    int tid = threadIdx.x;
    int tx = tid & 7;            // 8 -> 8 cols each
    int ty = tid >> 3;           // 16 -> 8 rows each

    const float* arow = g_attn + (size_t)(b * HEADS + h) * SEQ;
    for (int xint = tid; xint < SEQ; xint += 128) {
        float vv = arow[xint];
        A2[xint] = vv;
        A2[xint + SEQ] = vv;
    }
    __syncthreads();

    float acc[8][8];
    #pragma unroll
    for (int r = 0; r < 8; r++)
        #pragma unroll
        for (int s = 0; s < 8; s++) acc[r][s] = 0.f;

    const float* Vb = g_V + (size_t)b * SEQ * CH;
    int ibase = i0 + ty * 8;

    for (int j0 = 0; j0 < SEQ; j0 += 16) {
        #pragma unroll
        for (int q = 0; q < 2; q++) {
            int f = tid + q * 128;
            int row = f >> 4;        // 0..15
            int cq = f & 15;         // 0..15
            float4 vv = *(const float4*)(Vb + (size_t)(j0 + row) * CH + c0 + cq * 4);
            *(float4*)&Vs[row][cq * 4] = vv;
        }
        __syncthreads();
        #pragma unroll
        for (int jj = 0; jj < 16; jj++) {
            int abase = j0 + jj + SEQ - ibase;   // in [8, 4095]
            float av[8];
            #pragma unroll
            for (int r = 0; r < 8; r++) av[r] = A2[abase - r];
            float4 v0 = *(const float4*)&Vs[jj][tx * 8];
            float4 v1 = *(const float4*)&Vs[jj][tx * 8 + 4];
            float bv[8] = {v0.x, v0.y, v0.z, v0.w, v1.x, v1.y, v1.z, v1.w};
            #pragma unroll
            for (int r = 0; r < 8; r++)
                #pragma unroll
                for (int s = 0; s < 8; s++)
                    acc[r][s] += av[r] * bv[s];
        }
        __syncthreads();
    }

    #pragma unroll
    for (int r = 0; r < 8; r++) {
        float* op = g_oa + ((size_t)b * SEQ + ibase + r) * CH + c0 + tx * 8;
        *(float4*)op = make_float4(acc[r][0], acc[r][1], acc[r][2], acc[r][3]);
        *(float4*)(op + 4) = make_float4(acc[r][4], acc[r][5], acc[r][6], acc[r][7]);
    }
}

// ---------------- launch ------------------------------------------------------
extern "C" void kernel_launch(void* const* d_in, const int* in_sizes, int n_in,
                              void* d_out, int out_size) {
    const float* x  = (const float*)d_in[0];
    const float* Wq = (const float*)d_in[1];
    const float* Wk = (const float*)d_in[2];
    const float* Wv = (const float*)d_in[3];
    const float* Wp = (const float*)d_in[4];
    const float* bp = (const float*)d_in[5];
    float* out = (float*)d_out;

    // resolve device-global scratch addresses (host side, no allocation)
    float* dV;  cudaGetSymbolAddress((void**)&dV,  g_V);
    float* dOA; cudaGetSymbolAddress((void**)&dOA, g_oa);

    // 1) x mean over n
    xpart_kernel<<<dim3(16, BATCH), 256>>>(x);
    xmean_kernel<<<BATCH, CH>>>();
    // 2) u = SCALE * Wq(head-block)^T @ K_avg
    u_kernel<<<BATCH * HEADS, 256>>>(Wq, Wk);
    // 3) z = x . u
    z_kernel<<<BATCH * SEQ, 384>>>(x);
    // 4) softmax (+ 1/N fold)
    softmax_kernel<<<BATCH * HEADS, 256>>>();
    // 5) V = x @ Wv^T
    gemm_abt_kernel<false><<<dim3(CH / 128, (BATCH * SEQ) / 128), 256>>>(
        x, Wv, nullptr, dV, BATCH * SEQ, CH, CH);
    // 6) circulant attention
    circ_kernel<<<dim3(SEQ / 128, CH / 64, BATCH), 128>>>();
    // 7) out = oa @ Wp^T + bp
    gemm_abt_kernel<true><<<dim3(CH / 128, (BATCH * SEQ) / 128), 256>>>(
        dOA, Wp, bp, out, BATCH * SEQ, CH, CH);
}

// round 4
// speedup vs baseline: 1.1552x; 1.1552x over previous
#include <cuda_runtime.h>
#include <cuda_fp16.h>
#include <cstdint>

#define BATCH 2
#define SEQ   2048
#define CH    768
#define HEADS 12
#define HDIM  64
#define ATT_SCALE 0.125f   // HDIM^-0.5
#define OA_SCALE 4096.0f
#define OA_INV   (1.0f / 4096.0f)

// ---------------- scratch (static device arrays; no cudaMalloc) -------------
__device__ float g_xpart[BATCH * 16 * CH];
__device__ float g_xmean[BATCH * CH];
__device__ float g_u[BATCH * HEADS * CH];
__device__ float g_z[BATCH * HEADS * SEQ];
__device__ float g_attn[BATCH * HEADS * SEQ];   // softmax / SEQ (fp32)
__device__ float g_V[BATCH * SEQ * CH];

__device__ __half g_xhi[BATCH * SEQ * CH];
__device__ __half g_xlo[BATCH * SEQ * CH];
__device__ __half g_wvhi[CH * CH];
__device__ __half g_wvlo[CH * CH];
__device__ __half g_wphi[CH * CH];
__device__ __half g_wplo[CH * CH];
__device__ __half g_oahi[BATCH * SEQ * CH];     // oa * OA_SCALE, hi part
__device__ __half g_oalo[BATCH * SEQ * CH];     // oa * OA_SCALE, lo part

// ---------------- fp32 -> fp16 hi/lo split ----------------------------------
__global__ void split_kernel(const float* __restrict__ src,
                             __half* __restrict__ hi, __half* __restrict__ lo,
                             int n4) {
    int i = blockIdx.x * 256 + threadIdx.x;
    if (i >= n4) return;
    float4 v = ((const float4*)src)[i];
    __half hx = __float2half_rn(v.x), hy = __float2half_rn(v.y);
    __half hz = __float2half_rn(v.z), hw = __float2half_rn(v.w);
    __half lx = __float2half_rn(v.x - __half2float(hx));
    __half ly = __float2half_rn(v.y - __half2float(hy));
    __half lz = __float2half_rn(v.z - __half2float(hz));
    __half lw = __float2half_rn(v.w - __half2float(hw));
    ((__half2*)hi)[i * 2]     = __halves2half2(hx, hy);
    ((__half2*)hi)[i * 2 + 1] = __halves2half2(hz, hw);
    ((__half2*)lo)[i * 2]     = __halves2half2(lx, ly);
    ((__half2*)lo)[i * 2 + 1] = __halves2half2(lz, lw);
}

// ---------------- 1a: partial sums of x over n ------------------------------
__global__ void xpart_kernel(const float* __restrict__ x) {
    int b = blockIdx.y;
    int chunk = blockIdx.x;           // 16 chunks of 128 rows
    const float* xb = x + ((size_t)b * SEQ + (size_t)chunk * 128) * CH;
    for (int c = threadIdx.x; c < CH; c += 256) {
        float s = 0.f;
        #pragma unroll 8
        for (int n = 0; n < 128; n++) s += xb[(size_t)n * CH + c];
        g_xpart[(b * 16 + chunk) * CH + c] = s;
    }
}

// ---------------- 1b: reduce partials -> mean -------------------------------
__global__ void xmean_kernel() {
    int b = blockIdx.x;
    int c = threadIdx.x;              // 768 threads
    float s = 0.f;
    #pragma unroll
    for (int k = 0; k < 16; k++) s += g_xpart[(b * 16 + k) * CH + c];
    g_xmean[b * CH + c] = s * (1.0f / SEQ);
}

// ---------------- 2: u[b,h,c] = SCALE * sum_d Wq[h*64+d,c] * K_avg[b,h,d] ---
__global__ void u_kernel(const float* __restrict__ Wq, const float* __restrict__ Wk) {
    int b = blockIdx.x / HEADS;
    int h = blockIdx.x % HEADS;
    __shared__ float xm[CH];
    __shared__ float kavg[HDIM];
    for (int c = threadIdx.x; c < CH; c += 256) xm[c] = g_xmean[b * CH + c];
    __syncthreads();
    if (threadIdx.x < HDIM) {
        const float* wk = Wk + (size_t)(h * HDIM + threadIdx.x) * CH;
        float s = 0.f;
        #pragma unroll 8
        for (int c = 0; c < CH; c++) s += xm[c] * wk[c];
        kavg[threadIdx.x] = s;
    }
    __syncthreads();
    for (int c = threadIdx.x; c < CH; c += 256) {
        float s = 0.f;
        #pragma unroll 8
        for (int d = 0; d < HDIM; d++)
            s += Wq[(size_t)(h * HDIM + d) * CH + c] * kavg[d];
        g_u[(b * HEADS + h) * CH + c] = s * ATT_SCALE;
    }
}

// ---------------- 3: z[b,h,n] = x[b,n,:] . u[b,h,:] --------------------------
__global__ void z_kernel(const float* __restrict__ x) {
    int bn = blockIdx.x;
    int b = bn / SEQ;
    int n = bn % SEQ;
    __shared__ float xs[CH];
    const float* xr = x + (size_t)bn * CH;
    for (int c = threadIdx.x; c < CH; c += 384) xs[c] = xr[c];
    __syncthreads();
    int w = threadIdx.x >> 5;                  // 12 warps = 12 heads
    int lane = threadIdx.x & 31;
    const float* u = g_u + (size_t)(b * HEADS + w) * CH;
    float s = 0.f;
    #pragma unroll
    for (int c = lane; c < CH; c += 32) s += xs[c] * u[c];
    #pragma unroll
    for (int off = 16; off > 0; off >>= 1)
        s += __shfl_down_sync(0xffffffffu, s, off);
    if (lane == 0) g_z[(b * HEADS + w) * SEQ + n] = s;
}

// ---------------- 4: softmax over n per (b,h), fold 1/SEQ --------------------
__global__ void softmax_kernel() {
    __shared__ float red[256];
    int base = blockIdx.x * SEQ;
    int tid = threadIdx.x;
    float v[8];
    float m = -1e30f;
    #pragma unroll
    for (int k = 0; k < 8; k++) {
        v[k] = g_z[base + tid + k * 256];
        m = fmaxf(m, v[k]);
    }
    red[tid] = m; __syncthreads();
    for (int s = 128; s > 0; s >>= 1) {
        if (tid < s) red[tid] = fmaxf(red[tid], red[tid + s]);
        __syncthreads();
    }
    m = red[0]; __syncthreads();
    float sum = 0.f;
    #pragma unroll
    for (int k = 0; k < 8; k++) { v[k] = __expf(v[k] - m); sum += v[k]; }
    red[tid] = sum; __syncthreads();
    for (int s = 128; s > 0; s >>= 1) {
        if (tid < s) red[tid] += red[tid + s];
        __syncthreads();
    }
    float inv = 1.0f / (red[0] * (float)SEQ);
    #pragma unroll
    for (int k = 0; k < 8; k++) g_attn[base + tid + k * 256] = v[k] * inv;
}

// ================= warp-MMA fp16-split GEMM ==================================
// out[M,768] = (Ahi+Alo)[M,768] @ ((Bhi+Blo)[768,768])^T  (fp32 accum)
// 3 products: hi*hi + hi*lo + lo*hi.  CTA tile 128x128, K-stage 32, 256 thr,
// 8 warps as 2(M)x4(N), warp tile 64x32, mma.sync.m16n8k16.
// smem rows padded to 80B (20 u32): fragment loads provably conflict-free.
__device__ __forceinline__ void mma16816(float* c, const uint32_t* a, const uint32_t* b) {
    asm volatile(
        "mma.sync.aligned.m16n8k16.row.col.f32.f16.f16.f32 "
        "{%0,%1,%2,%3}, {%4,%5,%6,%7}, {%8,%9}, {%0,%1,%2,%3};\n"
        : "+f"(c[0]), "+f"(c[1]), "+f"(c[2]), "+f"(c[3])
        : "r"(a[0]), "r"(a[1]), "r"(a[2]), "r"(a[3]), "r"(b[0]), "r"(b[1]));
}

template <bool BIAS>
__global__ void __launch_bounds__(256) gemm_mma_kernel(
    const __half* __restrict__ Ahi, const __half* __restrict__ Alo,
    const __half* __restrict__ Bhi, const __half* __restrict__ Blo,
    const float* __restrict__ bias, float* __restrict__ out, float outscale)
{
    __shared__ uint32_t sAhi[128 * 20], sAlo[128 * 20];
    __shared__ uint32_t sBhi[128 * 20], sBlo[128 * 20];

    int tid = threadIdx.x;
    int m0 = blockIdx.y * 128;
    int n0 = blockIdx.x * 128;
    int w = tid >> 5, lane = tid & 31;
    int wm = w >> 2, wn = w & 3;           // 2 x 4 warp grid
    int g = lane >> 2, tig = lane & 3;

    float acc[4][4][4];
    #pragma unroll
    for (int mt = 0; mt < 4; mt++)
        #pragma unroll
        for (int nt = 0; nt < 4; nt++)
            #pragma unroll
            for (int r = 0; r < 4; r++) acc[mt][nt][r] = 0.f;

    // loader mapping: thread t -> row = t>>1 (0..127), hs = t&1 (16-half group)
    int lrow = tid >> 1;
    int hs = tid & 1;
    size_t goffA = (size_t)(m0 + lrow) * CH + hs * 16;   // + k0
    size_t goffB = (size_t)(n0 + lrow) * CH + hs * 16;
    int soff = lrow * 20 + hs * 8;                        // u32 index

    const int NSTAGE = CH / 32;   // 24
    uint4 pa0, pa1, pb0, pb1, pc0, pc1, pd0, pd1;

    // prologue: prefetch stage 0
    {
        pa0 = *(const uint4*)(Ahi + goffA);     pa1 = *(const uint4*)(Ahi + goffA + 8);
        pb0 = *(const uint4*)(Alo + goffA);     pb1 = *(const uint4*)(Alo + goffA + 8);
        pc0 = *(const uint4*)(Bhi + goffB);     pc1 = *(const uint4*)(Bhi + goffB + 8);
        pd0 = *(const uint4*)(Blo + goffB);     pd1 = *(const uint4*)(Blo + goffB + 8);
    }

    for (int s = 0; s < NSTAGE; s++) {
        // commit prefetched stage s to smem
        *(uint4*)(sAhi + soff) = pa0;  *(uint4*)(sAhi + soff + 4) = pa1;
        *(uint4*)(sAlo + soff) = pb0;  *(uint4*)(sAlo + soff + 4) = pb1;
        *(uint4*)(sBhi + soff) = pc0;  *(uint4*)(sBhi + soff + 4) = pc1;
        *(uint4*)(sBlo + soff) = pd0;  *(uint4*)(sBlo + soff + 4) = pd1;
        __syncthreads();

        // prefetch stage s+1
        if (s + 1 < NSTAGE) {
            size_t ga = goffA + (size_t)(s + 1) * 32;
            size_t gb = goffB + (size_t)(s + 1) * 32;
            pa0 = *(const uint4*)(Ahi + ga);  pa1 = *(const uint4*)(Ahi + ga + 8);
            pb0 = *(const uint4*)(Alo + ga);  pb1 = *(const uint4*)(Alo + ga + 8);
            pc0 = *(const uint4*)(Bhi + gb);  pc1 = *(const uint4*)(Bhi + gb + 8);
            pd0 = *(const uint4*)(Blo + gb);  pd1 = *(const uint4*)(Blo + gb + 8);
        }

        // compute stage s
        #pragma unroll
        for (int kk = 0; kk < 2; kk++) {
            uint32_t bh[4][2], bl[4][2];
            #pragma unroll
            for (int nt = 0; nt < 4; nt++) {
                int bi = (wn * 32 + nt * 8 + g) * 20 + kk * 8 + tig;
                bh[nt][0] = sBhi[bi];     bh[nt][1] = sBhi[bi + 4];
                bl[nt][0] = sBlo[bi];     bl[nt][1] = sBlo[bi + 4];
            }
            #pragma unroll
            for (int mt = 0; mt < 4; mt++) {
                int ai = (wm * 64 + mt * 16 + g) * 20 + kk * 8 + tig;
                uint32_t ah[4], al[4];
                ah[0] = sAhi[ai];         ah[1] = sAhi[ai + 160];
                ah[2] = sAhi[ai + 4];     ah[3] = sAhi[ai + 164];
                al[0] = sAlo[ai];         al[1] = sAlo[ai + 160];
                al[2] = sAlo[ai + 4];     al[3] = sAlo[ai + 164];
                #pragma unroll
                for (int nt = 0; nt < 4; nt++) {
                    mma16816(acc[mt][nt], ah, bh[nt]);   // hi*hi
                    mma16816(acc[mt][nt], ah, bl[nt]);   // hi*lo
                    mma16816(acc[mt][nt], al, bh[nt]);   // lo*hi
                }
            }
        }
        __syncthreads();
    }

    // epilogue
    #pragma unroll
    for (int mt = 0; mt < 4; mt++) {
        int r = m0 + wm * 64 + mt * 16 + g;
        #pragma unroll
        for (int nt = 0; nt < 4; nt++) {
            int c = n0 + wn * 32 + nt * 8 + tig * 2;
            float2 v0, v1;
            v0.x = acc[mt][nt][0] * outscale;
            v0.y = acc[mt][nt][1] * outscale;
            v1.x = acc[mt][nt][2] * outscale;
            v1.y = acc[mt][nt][3] * outscale;
            if (BIAS) {
                v0.x += bias[c];     v0.y += bias[c + 1];
                v1.x += bias[c];     v1.y += bias[c + 1];
            }
            *(float2*)(out + (size_t)r * CH + c)       = v0;
            *(float2*)(out + (size_t)(r + 8) * CH + c) = v1;
        }
    }
}

// ---------------- circulant: oa[b,i,c] = sum_j attn[b,h(c),(j-i)%N] * V[b,j,c]
// fp32 SIMT; epilogue writes oa * OA_SCALE as fp16 hi/lo for the out-proj GEMM.
__global__ void __launch_bounds__(128) circ_kernel() {
    __shared__ float A2[2 * SEQ];
    __shared__ float Vs[16][68];
    int b = blockIdx.z;
    int i0 = blockIdx.x * 128;
    int c0 = blockIdx.y * 64;
    int h = c0 / HDIM;
    int tid = threadIdx.x;
    int tx = tid & 7;
    int ty = tid >> 3;

    const float* arow = g_attn + (size_t)(b * HEADS + h) * SEQ;
    for (int xint = tid; xint < SEQ; xint += 128) {
        float vv = arow[xint];
        A2[xint] = vv;
        A2[xint + SEQ] = vv;
    }
    __syncthreads();

    float acc[8][8];
    #pragma unroll
    for (int r = 0; r < 8; r++)
        #pragma unroll
        for (int s = 0; s < 8; s++) acc[r][s] = 0.f;

    const float* Vb = g_V + (size_t)b * SEQ * CH;
    int ibase = i0 + ty * 8;

    for (int j0 = 0; j0 < SEQ; j0 += 16) {
        #pragma unroll
        for (int q = 0; q < 2; q++) {
            int f = tid + q * 128;
            int row = f >> 4;
            int cq = f & 15;
            float4 vv = *(const float4*)(Vb + (size_t)(j0 + row) * CH + c0 + cq * 4);
            *(float4*)&Vs[row][cq * 4] = vv;
        }
        __syncthreads();
        #pragma unroll
        for (int jj = 0; jj < 16; jj++) {
            int abase = j0 + jj + SEQ - ibase;
            float av[8];
            #pragma unroll
            for (int r = 0; r < 8; r++) av[r] = A2[abase - r];
            float4 v0 = *(const float4*)&Vs[jj][tx * 8];
            float4 v1 = *(const float4*)&Vs[jj][tx * 8 + 4];
            float bv[8] = {v0.x, v0.y, v0.z, v0.w, v1.x, v1.y, v1.z, v1.w};
            #pragma unroll
            for (int r = 0; r < 8; r++)
                #pragma unroll
                for (int s = 0; s < 8; s++)
                    acc[r][s] += av[r] * bv[s];
        }
        __syncthreads();
    }

    #pragma unroll
    for (int r = 0; r < 8; r++) {
        size_t idx = ((size_t)b * SEQ + ibase + r) * CH + c0 + tx * 8;
        #pragma unroll
        for (int p = 0; p < 4; p++) {
            float v0 = acc[r][p * 2]     * OA_SCALE;
            float v1 = acc[r][p * 2 + 1] * OA_SCALE;
            __half h0 = __float2half_rn(v0);
            __half h1 = __float2half_rn(v1);
            __half l0 = __float2half_rn(v0 - __half2float(h0));
            __half l1 = __float2half_rn(v1 - __half2float(h1));
            *(__half2*)(g_oahi + idx + p * 2) = __halves2half2(h0, h1);
            *(__half2*)(g_oalo + idx + p * 2) = __halves2half2(l0, l1);
        }
    }
}

// ---------------- launch ------------------------------------------------------
extern "C" void kernel_launch(void* const* d_in, const int* in_sizes, int n_in,
                              void* d_out, int out_size) {
    const float* x  = (const float*)d_in[0];
    const float* Wq = (const float*)d_in[1];
    const float* Wk = (const float*)d_in[2];
    const float* Wv = (const float*)d_in[3];
    const float* Wp = (const float*)d_in[4];
    const float* bp = (const float*)d_in[5];
    float* out = (float*)d_out;

    float* dV;    cudaGetSymbolAddress((void**)&dV,    g_V);
    __half* dxhi; cudaGetSymbolAddress((void**)&dxhi,  g_xhi);
    __half* dxlo; cudaGetSymbolAddress((void**)&dxlo,  g_xlo);
    __half* dvhi; cudaGetSymbolAddress((void**)&dvhi,  g_wvhi);
    __half* dvlo; cudaGetSymbolAddress((void**)&dvlo,  g_wvlo);
    __half* dphi; cudaGetSymbolAddress((void**)&dphi,  g_wphi);
    __half* dplo; cudaGetSymbolAddress((void**)&dplo,  g_wplo);
    __half* dohi; cudaGetSymbolAddress((void**)&dohi,  g_oahi);
    __half* dolo; cudaGetSymbolAddress((void**)&dolo,  g_oalo);

    // 0) fp16 hi/lo splits of x, Wv, Wp
    {
        int n4x = BATCH * SEQ * CH / 4;
        int n4w = CH * CH / 4;
        split_kernel<<<(n4x + 255) / 256, 256>>>(x,  dxhi, dxlo, n4x);
        split_kernel<<<(n4w + 255) / 256, 256>>>(Wv, dvhi, dvlo, n4w);
        split_kernel<<<(n4w + 255) / 256, 256>>>(Wp, dphi, dplo, n4w);
    }
    // 1) x mean over n
    xpart_kernel<<<dim3(16, BATCH), 256>>>(x);
    xmean_kernel<<<BATCH, CH>>>();
    // 2) u = SCALE * Wq(head-block)^T @ K_avg
    u_kernel<<<BATCH * HEADS, 256>>>(Wq, Wk);
    // 3) z = x . u
    z_kernel<<<BATCH * SEQ, 384>>>(x);
    // 4) softmax (+ 1/N fold)
    softmax_kernel<<<BATCH * HEADS, 256>>>();
    // 5) V = x @ Wv^T (warp MMA, fp16 split, fp32 out)
    gemm_mma_kernel<false><<<dim3(CH / 128, (BATCH * SEQ) / 128), 256>>>(
        dxhi, dxlo, dvhi, dvlo, nullptr, dV, 1.0f);
    // 6) circulant attention (fp32 SIMT) -> oa hi/lo (scaled)
    circ_kernel<<<dim3(SEQ / 128, CH / 64, BATCH), 128>>>();
    // 7) out = oa @ Wp^T + bp (warp MMA, unscale in epilogue)
    gemm_mma_kernel<true><<<dim3(CH / 128, (BATCH * SEQ) / 128), 256>>>(
        dohi, dolo, dphi, dplo, bp, out, OA_INV);
}

// round 5
// speedup vs baseline: 1.7760x; 1.5374x over previous
#include <cuda_runtime.h>
#include <cuda_fp16.h>
#include <cstdint>

#define BATCH 2
#define SEQ   2048
#define CH    768
#define HEADS 12
#define HDIM  64
#define ATT_SCALE 0.125f    // HDIM^-0.5
#define OA_SCALE 4096.0f    // folded into attn fp16 scaling
#define OA_INV   (1.0f / 4096.0f)

// ---------------- scratch (static device arrays; no cudaMalloc) -------------
__device__ float g_xpart[BATCH * 64 * CH];
__device__ float g_xmean[BATCH * CH];
__device__ float g_u[BATCH * HEADS * CH];
__device__ float g_z[BATCH * HEADS * SEQ];
__device__ float g_attn[BATCH * HEADS * SEQ];   // softmax / SEQ (fp32)

__device__ __half g_xhi[BATCH * SEQ * CH];
__device__ __half g_xlo[BATCH * SEQ * CH];
__device__ __half g_wvhi[CH * CH];
__device__ __half g_wvlo[CH * CH];
__device__ __half g_wphi[CH * CH];
__device__ __half g_wplo[CH * CH];
__device__ __half g_vhi[BATCH * SEQ * CH];      // V hi/lo (from V-proj epilogue)
__device__ __half g_vlo[BATCH * SEQ * CH];
__device__ __half g_oahi[BATCH * SEQ * CH];     // oa * OA_SCALE hi/lo
__device__ __half g_oalo[BATCH * SEQ * CH];

// ---------------- fp32 -> fp16 hi/lo split ----------------------------------
__global__ void split_kernel(const float* __restrict__ src,
                             __half* __restrict__ hi, __half* __restrict__ lo,
                             int n4) {
    int i = blockIdx.x * 256 + threadIdx.x;
    if (i >= n4) return;
    float4 v = ((const float4*)src)[i];
    __half hx = __float2half_rn(v.x), hy = __float2half_rn(v.y);
    __half hz = __float2half_rn(v.z), hw = __float2half_rn(v.w);
    __half lx = __float2half_rn(v.x - __half2float(hx));
    __half ly = __float2half_rn(v.y - __half2float(hy));
    __half lz = __float2half_rn(v.z - __half2float(hz));
    __half lw = __float2half_rn(v.w - __half2float(hw));
    ((__half2*)hi)[i * 2]     = __halves2half2(hx, hy);
    ((__half2*)hi)[i * 2 + 1] = __halves2half2(hz, hw);
    ((__half2*)lo)[i * 2]     = __halves2half2(lx, ly);
    ((__half2*)lo)[i * 2 + 1] = __halves2half2(lz, lw);
}

// ---------------- 1a: partial sums of x over n (64 chunks of 32 rows) -------
__global__ void xpart_kernel(const float* __restrict__ x) {
    int b = blockIdx.y;
    int chunk = blockIdx.x;           // 64 chunks of 32 rows
    const float* xb = x + ((size_t)b * SEQ + (size_t)chunk * 32) * CH;
    for (int c = threadIdx.x; c < CH; c += 256) {
        float s = 0.f;
        #pragma unroll 8
        for (int n = 0; n < 32; n++) s += xb[(size_t)n * CH + c];
        g_xpart[(b * 64 + chunk) * CH + c] = s;
    }
}

// ---------------- 1b: reduce partials -> mean -------------------------------
__global__ void xmean_kernel() {
    int b = blockIdx.x;
    int c = threadIdx.x;              // 768 threads
    float s = 0.f;
    #pragma unroll
    for (int k = 0; k < 64; k++) s += g_xpart[(b * 64 + k) * CH + c];
    g_xmean[b * CH + c] = s * (1.0f / SEQ);
}

// ---------------- 2: u[b,h,c] = SCALE * sum_d Wq[h*64+d,c] * K_avg[b,h,d] ---
__global__ void u_kernel(const float* __restrict__ Wq, const float* __restrict__ Wk) {
    int b = blockIdx.x / HEADS;
    int h = blockIdx.x % HEADS;
    __shared__ float xm[CH];
    __shared__ float kavg[HDIM];
    for (int c = threadIdx.x; c < CH; c += 256) xm[c] = g_xmean[b * CH + c];
    __syncthreads();
    if (threadIdx.x < HDIM) {
        const float* wk = Wk + (size_t)(h * HDIM + threadIdx.x) * CH;
        float s = 0.f;
        #pragma unroll 8
        for (int c = 0; c < CH; c++) s += xm[c] * wk[c];
        kavg[threadIdx.x] = s;
    }
    __syncthreads();
    for (int c = threadIdx.x; c < CH; c += 256) {
        float s = 0.f;
        #pragma unroll 8
        for (int d = 0; d < HDIM; d++)
            s += Wq[(size_t)(h * HDIM + d) * CH + c] * kavg[d];
        g_u[(b * HEADS + h) * CH + c] = s * ATT_SCALE;
    }
}

// ---------------- 3: z[b,h,n] = x[b,n,:] . u[b,h,:] --------------------------
__global__ void z_kernel(const float* __restrict__ x) {
    int bn = blockIdx.x;
    int b = bn / SEQ;
    int n = bn % SEQ;
    __shared__ float xs[CH];
    const float* xr = x + (size_t)bn * CH;
    for (int c = threadIdx.x; c < CH; c += 384) xs[c] = xr[c];
    __syncthreads();
    int w = threadIdx.x >> 5;                  // 12 warps = 12 heads
    int lane = threadIdx.x & 31;
    const float* u = g_u + (size_t)(b * HEADS + w) * CH;
    float s = 0.f;
    #pragma unroll
    for (int c = lane; c < CH; c += 32) s += xs[c] * u[c];
    #pragma unroll
    for (int off = 16; off > 0; off >>= 1)
        s += __shfl_down_sync(0xffffffffu, s, off);
    if (lane == 0) g_z[(b * HEADS + w) * SEQ + n] = s;
}

// ---------------- 4: softmax over n per (b,h), fold 1/SEQ --------------------
__global__ void softmax_kernel() {
    __shared__ float red[256];
    int base = blockIdx.x * SEQ;
    int tid = threadIdx.x;
    float v[8];
    float m = -1e30f;
    #pragma unroll
    for (int k = 0; k < 8; k++) {
        v[k] = g_z[base + tid + k * 256];
        m = fmaxf(m, v[k]);
    }
    red[tid] = m; __syncthreads();
    for (int s = 128; s > 0; s >>= 1) {
        if (tid < s) red[tid] = fmaxf(red[tid], red[tid + s]);
        __syncthreads();
    }
    m = red[0]; __syncthreads();
    float sum = 0.f;
    #pragma unroll
    for (int k = 0; k < 8; k++) { v[k] = __expf(v[k] - m); sum += v[k]; }
    red[tid] = sum; __syncthreads();
    for (int s = 128; s > 0; s >>= 1) {
        if (tid < s) red[tid] += red[tid + s];
        __syncthreads();
    }
    float inv = 1.0f / (red[0] * (float)SEQ);
    #pragma unroll
    for (int k = 0; k < 8; k++) g_attn[base + tid + k * 256] = v[k] * inv;
}

// ================= warp-MMA building blocks ==================================
__device__ __forceinline__ void mma16816(float* c, const uint32_t* a, const uint32_t* b) {
    asm volatile(
        "mma.sync.aligned.m16n8k16.row.col.f32.f16.f16.f32 "
        "{%0,%1,%2,%3}, {%4,%5,%6,%7}, {%8,%9}, {%0,%1,%2,%3};\n"
        : "+f"(c[0]), "+f"(c[1]), "+f"(c[2]), "+f"(c[3])
        : "r"(a[0]), "r"(a[1]), "r"(a[2]), "r"(a[3]), "r"(b[0]), "r"(b[1]));
}

__device__ __forceinline__ uint32_t smem_u32(const void* p) {
    uint32_t a;
    asm("{ .reg .u64 t; cvta.to.shared.u64 t, %1; cvt.u32.u64 %0, t; }"
        : "=r"(a) : "l"(p));
    return a;
}

__device__ __forceinline__ void ldmatrix_x4_trans(uint32_t* r, uint32_t addr) {
    asm volatile(
        "ldmatrix.sync.aligned.m8n8.x4.trans.shared.b16 {%0,%1,%2,%3}, [%4];"
        : "=r"(r[0]), "=r"(r[1]), "=r"(r[2]), "=r"(r[3]) : "r"(addr));
}

// ================= warp-MMA fp16-split projection GEMM =======================
// out = (Ahi+Alo)[M,768] @ ((Bhi+Blo)[768,768])^T, fp32 accum, 3 products.
// MODE 1: fp32 out + bias (* outscale). MODE 2: fp16 hi/lo out.
template <int MODE>
__global__ void __launch_bounds__(256) gemm_mma_kernel(
    const __half* __restrict__ Ahi, const __half* __restrict__ Alo,
    const __half* __restrict__ Bhi, const __half* __restrict__ Blo,
    const float* __restrict__ bias, float* __restrict__ out,
    __half* __restrict__ outhi, __half* __restrict__ outlo, float outscale)
{
    __shared__ uint32_t sAhi[128 * 20], sAlo[128 * 20];
    __shared__ uint32_t sBhi[128 * 20], sBlo[128 * 20];

    int tid = threadIdx.x;
    int m0 = blockIdx.y * 128;
    int n0 = blockIdx.x * 128;
    int w = tid >> 5, lane = tid & 31;
    int wm = w >> 2, wn = w & 3;
    int g = lane >> 2, tig = lane & 3;

    float acc[4][4][4];
    #pragma unroll
    for (int mt = 0; mt < 4; mt++)
        #pragma unroll
        for (int nt = 0; nt < 4; nt++)
            #pragma unroll
            for (int r = 0; r < 4; r++) acc[mt][nt][r] = 0.f;

    int lrow = tid >> 1;
    int hs = tid & 1;
    size_t goffA = (size_t)(m0 + lrow) * CH + hs * 16;
    size_t goffB = (size_t)(n0 + lrow) * CH + hs * 16;
    int soff = lrow * 20 + hs * 8;

    const int NSTAGE = CH / 32;   // 24
    uint4 pa0, pa1, pb0, pb1, pc0, pc1, pd0, pd1;
    pa0 = *(const uint4*)(Ahi + goffA);  pa1 = *(const uint4*)(Ahi + goffA + 8);
    pb0 = *(const uint4*)(Alo + goffA);  pb1 = *(const uint4*)(Alo + goffA + 8);
    pc0 = *(const uint4*)(Bhi + goffB);  pc1 = *(const uint4*)(Bhi + goffB + 8);
    pd0 = *(const uint4*)(Blo + goffB);  pd1 = *(const uint4*)(Blo + goffB + 8);

    for (int s = 0; s < NSTAGE; s++) {
        *(uint4*)(sAhi + soff) = pa0;  *(uint4*)(sAhi + soff + 4) = pa1;
        *(uint4*)(sAlo + soff) = pb0;  *(uint4*)(sAlo + soff + 4) = pb1;
        *(uint4*)(sBhi + soff) = pc0;  *(uint4*)(sBhi + soff + 4) = pc1;
        *(uint4*)(sBlo + soff) = pd0;  *(uint4*)(sBlo + soff + 4) = pd1;
        __syncthreads();

        if (s + 1 < NSTAGE) {
            size_t ga = goffA + (size_t)(s + 1) * 32;
            size_t gb = goffB + (size_t)(s + 1) * 32;
            pa0 = *(const uint4*)(Ahi + ga);  pa1 = *(const uint4*)(Ahi + ga + 8);
            pb0 = *(const uint4*)(Alo + ga);  pb1 = *(const uint4*)(Alo + ga + 8);
            pc0 = *(const uint4*)(Bhi + gb);  pc1 = *(const uint4*)(Bhi + gb + 8);
            pd0 = *(const uint4*)(Blo + gb);  pd1 = *(const uint4*)(Blo + gb + 8);
        }

        #pragma unroll
        for (int kk = 0; kk < 2; kk++) {
            uint32_t bh[4][2], bl[4][2];
            #pragma unroll
            for (int nt = 0; nt < 4; nt++) {
                int bi = (wn * 32 + nt * 8 + g) * 20 + kk * 8 + tig;
                bh[nt][0] = sBhi[bi];     bh[nt][1] = sBhi[bi + 4];
                bl[nt][0] = sBlo[bi];     bl[nt][1] = sBlo[bi + 4];
            }
            #pragma unroll
            for (int mt = 0; mt < 4; mt++) {
                int ai = (wm * 64 + mt * 16 + g) * 20 + kk * 8 + tig;
                uint32_t ah[4], al[4];
                ah[0] = sAhi[ai];         ah[1] = sAhi[ai + 160];
                ah[2] = sAhi[ai + 4];     ah[3] = sAhi[ai + 164];
                al[0] = sAlo[ai];         al[1] = sAlo[ai + 160];
                al[2] = sAlo[ai + 4];     al[3] = sAlo[ai + 164];
                #pragma unroll
                for (int nt = 0; nt < 4; nt++) {
                    mma16816(acc[mt][nt], ah, bh[nt]);
                    mma16816(acc[mt][nt], ah, bl[nt]);
                    mma16816(acc[mt][nt], al, bh[nt]);
                }
            }
        }
        __syncthreads();
    }

    #pragma unroll
    for (int mt = 0; mt < 4; mt++) {
        int r = m0 + wm * 64 + mt * 16 + g;
        #pragma unroll
        for (int nt = 0; nt < 4; nt++) {
            int c = n0 + wn * 32 + nt * 8 + tig * 2;
            if (MODE == 1) {
                float2 v0, v1;
                v0.x = acc[mt][nt][0] * outscale + bias[c];
                v0.y = acc[mt][nt][1] * outscale + bias[c + 1];
                v1.x = acc[mt][nt][2] * outscale + bias[c];
                v1.y = acc[mt][nt][3] * outscale + bias[c + 1];
                *(float2*)(out + (size_t)r * CH + c)       = v0;
                *(float2*)(out + (size_t)(r + 8) * CH + c) = v1;
            } else {
                #pragma unroll
                for (int half_row = 0; half_row < 2; half_row++) {
                    float vx = acc[mt][nt][half_row * 2];
                    float vy = acc[mt][nt][half_row * 2 + 1];
                    __half hx = __float2half_rn(vx);
                    __half hy = __float2half_rn(vy);
                    __half lx = __float2half_rn(vx - __half2float(hx));
                    __half ly = __float2half_rn(vy - __half2float(hy));
                    size_t idx = (size_t)(r + half_row * 8) * CH + c;
                    *(__half2*)(outhi + idx) = __halves2half2(hx, hy);
                    *(__half2*)(outlo + idx) = __halves2half2(lx, ly);
                }
            }
        }
    }
}

// ================= circulant attention on tensor cores =======================
// oa[b,i,c] = sum_j attn2[(j-i) mod N] * V[j,c],  attn2 = attn/N * OA_SCALE
// A-fragments read directly from doubled attn smem (base + 1-half-shifted copy,
// parity-selected per thread). a3 == a0 by circulant shift invariance.
// V (hi/lo fp16) staged K-major in smem, B-fragments via ldmatrix.x4.trans.
// CTA: one (b, h, 128-row i-tile). 256 thr, 8 warps 2(M)x4(N), warp 64x16.
//
// dyn smem (halves): A2hi[4096] @0, A2hi_s[4096] @4096, A2lo @8192,
// A2lo_s @12288, V tiles @16384: (buf*2+arr)*4608, tile = 64 rows x 72 halves.
#define CIRC_SMEM_BYTES ((16384 + 4 * 4608) * 2)

__global__ void __launch_bounds__(256) circ_mma_kernel() {
    extern __shared__ __half dsm[];
    __half* A2hi  = dsm;
    __half* A2hiS = dsm + 4096;
    __half* A2lo  = dsm + 8192;
    __half* A2loS = dsm + 12288;
    __half* Vbase = dsm + 16384;

    int tid = threadIdx.x;
    int i0 = blockIdx.x * 128;
    int h  = blockIdx.y;
    int b  = blockIdx.z;
    int c0 = h * HDIM;
    int w = tid >> 5, lane = tid & 31;
    int wm = w >> 2, wn = w & 3;        // 2(M) x 4(N)
    int g = lane >> 2, tig = lane & 3;

    // ---- fill doubled + shifted attn arrays (scaled, fp16 hi/lo) ----
    const float* arow = g_attn + (size_t)(b * HEADS + h) * SEQ;
    for (int t = tid; t < SEQ; t += 256) {
        float a = arow[t] * OA_SCALE;
        __half hi = __float2half_rn(a);
        __half lo = __float2half_rn(a - __half2float(hi));
        A2hi[t] = hi;  A2hi[t + SEQ] = hi;
        A2lo[t] = lo;  A2lo[t + SEQ] = lo;
    }
    __syncthreads();
    for (int t = tid; t < 2 * SEQ - 1; t += 256) {
        A2hiS[t] = A2hi[t + 1];
        A2loS[t] = A2lo[t + 1];
    }
    if (tid == 0) { A2hiS[2 * SEQ - 1] = __float2half_rn(0.f); A2loS[2 * SEQ - 1] = __float2half_rn(0.f); }

    // ---- A-fragment lattice pointers (per thread, parity-fixed) ----
    int ob = SEQ + 2 * tig - (i0 + wm * 64 + g);
    int par = ob & 1;
    const uint32_t* PhiBase = (const uint32_t*)(par ? A2hiS : A2hi) + ((ob - par) >> 1);
    const uint32_t* PloBase = (const uint32_t*)(par ? A2loS : A2lo) + ((ob - par) >> 1);

    // ---- V loader mapping: 512 uint4 per array per 64-row chunk ----
    int u = tid;
    int vrow = u >> 3, vcg = u & 7;       // rows 0..31 pass A; +32 pass B
    const __half* gvh = g_vhi + ((size_t)b * SEQ + vrow) * CH + c0 + vcg * 8;
    const __half* gvl = g_vlo + ((size_t)b * SEQ + vrow) * CH + c0 + vcg * 8;
    // smem store offsets (halves): row*72 + vcg*8
    int svo_a = vrow * 72 + vcg * 8;
    int svo_b = (vrow + 32) * 72 + vcg * 8;

    // ---- ldmatrix address components ----
    int mrow = ((lane >> 3) & 1) * 8 + (lane & 7);   // k-row within 16-row block
    int ncol = wn * 16 + (lane >> 4) * 8;            // n column
    uint32_t svAddrPart = (uint32_t)(mrow * 144 + ncol * 2);
    uint32_t sVu32 = smem_u32(Vbase);

    float acc[4][2][4];
    #pragma unroll
    for (int mt = 0; mt < 4; mt++)
        #pragma unroll
        for (int nt = 0; nt < 2; nt++)
            #pragma unroll
            for (int r = 0; r < 4; r++) acc[mt][nt][r] = 0.f;

    // prefetch chunk 0
    uint4 pfh0, pfh1, pfl0, pfl1;
    pfh0 = *(const uint4*)gvh;
    pfh1 = *(const uint4*)(gvh + 32 * CH);
    pfl0 = *(const uint4*)gvl;
    pfl1 = *(const uint4*)(gvl + 32 * CH);

    __syncthreads();   // attn arrays ready

    const int NCHUNK = SEQ / 64;   // 32
    for (int c = 0; c < NCHUNK; c++) {
        int buf = c & 1;
        __half* sVhi = Vbase + (buf * 2 + 0) * 4608;
        __half* sVlo = Vbase + (buf * 2 + 1) * 4608;
        *(uint4*)(sVhi + svo_a) = pfh0;
        *(uint4*)(sVhi + svo_b) = pfh1;
        *(uint4*)(sVlo + svo_a) = pfl0;
        *(uint4*)(sVlo + svo_b) = pfl1;
        __syncthreads();

        if (c + 1 < NCHUNK) {
            size_t adv = (size_t)(c + 1) * 64 * CH;
            pfh0 = *(const uint4*)(gvh + adv);
            pfh1 = *(const uint4*)(gvh + adv + 32 * CH);
            pfl0 = *(const uint4*)(gvl + adv);
            pfl1 = *(const uint4*)(gvl + adv + 32 * CH);
        }

        // A lattice loads for this chunk (15 u32 per array)
        const uint32_t* Phi = PhiBase + 32 * c;
        const uint32_t* Plo = PloBase + 32 * c;
        uint32_t ehi[7], elo[7], fhi[8], flo[8];
        #pragma unroll
        for (int t = 0; t < 7; t++) { ehi[t] = Phi[8 * t - 24]; elo[t] = Plo[8 * t - 24]; }
        #pragma unroll
        for (int t = 0; t < 8; t++) { fhi[t] = Phi[8 * t - 28]; flo[t] = Plo[8 * t - 28]; }

        uint32_t sVhiAddr = sVu32 + (uint32_t)(buf * 2 + 0) * 9216u + svAddrPart;
        uint32_t sVloAddr = sVu32 + (uint32_t)(buf * 2 + 1) * 9216u + svAddrPart;

        #pragma unroll
        for (int kk = 0; kk < 4; kk++) {
            uint32_t bh[4], bl[4];
            ldmatrix_x4_trans(bh, sVhiAddr + kk * 2304u);
            ldmatrix_x4_trans(bl, sVloAddr + kk * 2304u);
            #pragma unroll
            for (int mt = 0; mt < 4; mt++) {
                int d3 = kk - mt + 3;      // 0..6
                uint32_t ah[4] = {ehi[d3], fhi[d3], fhi[d3 + 1], ehi[d3]};
                uint32_t al[4] = {elo[d3], flo[d3], flo[d3 + 1], elo[d3]};
                mma16816(acc[mt][0], ah, bh);
                mma16816(acc[mt][0], ah, bl);
                mma16816(acc[mt][0], al, bh);
                uint32_t bh1[2] = {bh[2], bh[3]};
                uint32_t bl1[2] = {bl[2], bl[3]};
                mma16816(acc[mt][1], ah, bh1);
                mma16816(acc[mt][1], ah, bl1);
                mma16816(acc[mt][1], al, bh1);
            }
        }
        __syncthreads();
    }

    // ---- epilogue: write oa*OA_SCALE as fp16 hi/lo ----
    #pragma unroll
    for (int mt = 0; mt < 4; mt++) {
        int r = i0 + wm * 64 + mt * 16 + g;
        #pragma unroll
        for (int nt = 0; nt < 2; nt++) {
            int cc = c0 + wn * 16 + nt * 8 + tig * 2;
            #pragma unroll
            for (int hr = 0; hr < 2; hr++) {
                float vx = acc[mt][nt][hr * 2];
                float vy = acc[mt][nt][hr * 2 + 1];
                __half hx = __float2half_rn(vx);
                __half hy = __float2half_rn(vy);
                __half lx = __float2half_rn(vx - __half2float(hx));
                __half ly = __float2half_rn(vy - __half2float(hy));
                size_t idx = (size_t)(b * SEQ + r + hr * 8) * CH + cc;
                *(__half2*)(g_oahi + idx) = __halves2half2(hx, hy);
                *(__half2*)(g_oalo + idx) = __halves2half2(lx, ly);
            }
        }
    }
}

// ---------------- launch ------------------------------------------------------
extern "C" void kernel_launch(void* const* d_in, const int* in_sizes, int n_in,
                              void* d_out, int out_size) {
    const float* x  = (const float*)d_in[0];
    const float* Wq = (const float*)d_in[1];
    const float* Wk = (const float*)d_in[2];
    const float* Wv = (const float*)d_in[3];
    const float* Wp = (const float*)d_in[4];
    const float* bp = (const float*)d_in[5];
    float* out = (float*)d_out;

    __half* dxhi; cudaGetSymbolAddress((void**)&dxhi,  g_xhi);
    __half* dxlo; cudaGetSymbolAddress((void**)&dxlo,  g_xlo);
    __half* dvhi; cudaGetSymbolAddress((void**)&dvhi,  g_wvhi);
    __half* dvlo; cudaGetSymbolAddress((void**)&dvlo,  g_wvlo);
    __half* dphi; cudaGetSymbolAddress((void**)&dphi,  g_wphi);
    __half* dplo; cudaGetSymbolAddress((void**)&dplo,  g_wplo);
    __half* dVhi; cudaGetSymbolAddress((void**)&dVhi,  g_vhi);
    __half* dVlo; cudaGetSymbolAddress((void**)&dVlo,  g_vlo);
    __half* dohi; cudaGetSymbolAddress((void**)&dohi,  g_oahi);
    __half* dolo; cudaGetSymbolAddress((void**)&dolo,  g_oalo);

    cudaFuncSetAttribute(circ_mma_kernel,
                         cudaFuncAttributeMaxDynamicSharedMemorySize, CIRC_SMEM_BYTES);

    // 0) fp16 hi/lo splits of x, Wv, Wp
    {
        int n4x = BATCH * SEQ * CH / 4;
        int n4w = CH * CH / 4;
        split_kernel<<<(n4x + 255) / 256, 256>>>(x,  dxhi, dxlo, n4x);
        split_kernel<<<(n4w + 255) / 256, 256>>>(Wv, dvhi, dvlo, n4w);
        split_kernel<<<(n4w + 255) / 256, 256>>>(Wp, dphi, dplo, n4w);
    }
    // 1) x mean over n
    xpart_kernel<<<dim3(64, BATCH), 256>>>(x);
    xmean_kernel<<<BATCH, CH>>>();
    // 2) u = SCALE * Wq(head-block)^T @ K_avg
    u_kernel<<<BATCH * HEADS, 256>>>(Wq, Wk);
    // 3) z = x . u
    z_kernel<<<BATCH * SEQ, 384>>>(x);
    // 4) softmax (+ 1/N fold)
    softmax_kernel<<<BATCH * HEADS, 256>>>();
    // 5) V = x @ Wv^T  (warp MMA, fp16 split -> fp16 hi/lo out)
    gemm_mma_kernel<2><<<dim3(CH / 128, (BATCH * SEQ) / 128), 256>>>(
        dxhi, dxlo, dvhi, dvlo, nullptr, nullptr, dVhi, dVlo, 1.0f);
    // 6) circulant attention (tensor cores) -> oa hi/lo (scaled)
    circ_mma_kernel<<<dim3(SEQ / 128, HEADS, BATCH), 256, CIRC_SMEM_BYTES>>>();
    // 7) out = oa @ Wp^T + bp (warp MMA, unscale)
    gemm_mma_kernel<1><<<dim3(CH / 128, (BATCH * SEQ) / 128), 256>>>(
        dohi, dolo, dphi, dplo, bp, out, nullptr, nullptr, OA_INV);
}